// round 1
// baseline (speedup 1.0000x reference)
#include <cuda_runtime.h>
#include <cuda_bf16.h>

// RoIAlign, aligned=True style (off=0.5), SR=2, OUT 7x7, SCALE=0.25
// feat: (B=2, C=256, H=200, W=336) fp32 NCHW
// rois: (N=1000, 5) [bidx, x1, y1, x2, y2] fp32
// out:  (N, C, 7, 7) fp32

#define C_    256
#define H_    200
#define W_    336
#define OUTH  7
#define OUTW  7

__global__ __launch_bounds__(256) void roi_align_kernel(
    const float* __restrict__ feat,
    const float* __restrict__ rois,
    float* __restrict__ out,
    int total)
{
    int idx = blockIdx.x * blockDim.x + threadIdx.x;
    if (idx >= total) return;

    int pw = idx % OUTW;
    int t  = idx / OUTW;
    int ph = t % OUTH;
    t /= OUTH;
    int c = t % C_;
    int n = t / C_;

    const float* r = rois + n * 5;
    int   b  = (int)__ldg(r + 0);
    float sx = __ldg(r + 1) * 0.25f - 0.5f;
    float sy = __ldg(r + 2) * 0.25f - 0.5f;
    float ex = __ldg(r + 3) * 0.25f - 0.5f;
    float ey = __ldg(r + 4) * 0.25f - 0.5f;
    float bw = (ex - sx) / (float)OUTW;
    float bh = (ey - sy) / (float)OUTH;

    const float* fp = feat + ((size_t)b * C_ + c) * (size_t)(H_ * W_);

    float acc = 0.0f;

    #pragma unroll
    for (int iy = 0; iy < 2; iy++) {
        float y = sy + ((float)ph + (0.25f + 0.5f * iy)) * bh;
        if (y > -1.0f && y < (float)H_) {
            float y0 = fmaxf(y, 0.0f);
            int ylo = (int)floorf(y0);
            int yhi;
            float ly;
            if (ylo >= H_ - 1) { ylo = H_ - 1; yhi = H_ - 1; ly = 0.0f; }
            else               { yhi = ylo + 1; ly = y0 - (float)ylo; }

            const float* row0 = fp + ylo * W_;
            const float* row1 = fp + yhi * W_;
            float wy1 = ly, wy0 = 1.0f - ly;

            #pragma unroll
            for (int ix = 0; ix < 2; ix++) {
                float x = sx + ((float)pw + (0.25f + 0.5f * ix)) * bw;
                if (x > -1.0f && x < (float)W_) {
                    float x0 = fmaxf(x, 0.0f);
                    int xlo = (int)floorf(x0);
                    int xhi;
                    float lx;
                    if (xlo >= W_ - 1) { xlo = W_ - 1; xhi = W_ - 1; lx = 0.0f; }
                    else               { xhi = xlo + 1; lx = x0 - (float)xlo; }

                    float v00 = __ldg(row0 + xlo);
                    float v01 = __ldg(row0 + xhi);
                    float v10 = __ldg(row1 + xlo);
                    float v11 = __ldg(row1 + xhi);

                    float wx1 = lx, wx0 = 1.0f - lx;
                    acc += (v00 * wy0 + v10 * wy1) * wx0
                         + (v01 * wy0 + v11 * wy1) * wx1;
                }
            }
        }
    }

    out[idx] = acc * 0.25f;
}

extern "C" void kernel_launch(void* const* d_in, const int* in_sizes, int n_in,
                              void* d_out, int out_size)
{
    const float* feat = (const float*)d_in[0];
    const float* rois = (const float*)d_in[1];
    float* out = (float*)d_out;

    int total = out_size;  // N*C*7*7
    int threads = 256;
    int blocks = (total + threads - 1) / threads;
    roi_align_kernel<<<blocks, threads>>>(feat, rois, out, total);
}

// round 2
// speedup vs baseline: 1.6172x; 1.6172x over previous
#include <cuda_runtime.h>
#include <cuda_fp16.h>

// RoIAlign via NHWC fp16 relayout.
// feat: (B=2, C=256, H=200, W=336) fp32 NCHW
// rois: (N=1000, 5) [bidx, x1, y1, x2, y2] fp32
// out:  (N, 256, 7, 7) fp32

#define B_    2
#define C_    256
#define H_    200
#define W_    336
#define OUTH  7
#define OUTW  7
#define NBIN  49

// NHWC fp16 scratch: [B][H][W][C]
__device__ __half g_feat16[(size_t)B_ * H_ * W_ * C_];

// ---------------------------------------------------------------------------
// Kernel 1: NCHW fp32 -> NHWC fp16 transpose.
// grid (ceil(W/32), B*H, C/32), block (32, 8). smem tile 32x33.
// ---------------------------------------------------------------------------
__global__ __launch_bounds__(256) void transpose_kernel(const float* __restrict__ feat)
{
    __shared__ float tile[32][33];

    int xt = blockIdx.x * 32;
    int by = blockIdx.y;            // b*H + y
    int b  = by / H_;
    int y  = by % H_;
    int c0 = blockIdx.z * 32;
    int tx = threadIdx.x;
    int ty = threadIdx.y;

    const float* src = feat + ((size_t)(b * C_ + c0) * H_ + y) * W_;

    #pragma unroll
    for (int k = 0; k < 4; k++) {
        int c = ty + k * 8;
        int x = xt + tx;
        float v = 0.0f;
        if (x < W_) v = __ldg(src + (size_t)c * (H_ * W_) + x);
        tile[c][tx] = v;
    }
    __syncthreads();

    __half* dst = g_feat16 + ((size_t)(b * H_ + y) * W_) * C_;
    #pragma unroll
    for (int k = 0; k < 4; k++) {
        int xx = ty + k * 8;
        int x  = xt + xx;
        if (x < W_)
            dst[(size_t)x * C_ + c0 + tx] = __float2half(tile[tx][xx]);
    }
}

// ---------------------------------------------------------------------------
// Kernel 2: gather. grid (N, 2): blockIdx.x = roi, blockIdx.y = channel half.
// block 256 = 8 warps. Each warp handles one bin at a time (strided by 8),
// lane covers 4 channels (uint2 = 4 fp16). Results staged in smem [128][49],
// then one coalesced 25KB store per block.
// ---------------------------------------------------------------------------
__global__ __launch_bounds__(256) void roi_gather_kernel(
    const float* __restrict__ rois,
    float* __restrict__ out)
{
    __shared__ float sout[128 * NBIN];   // [c_local][bin], 25088 B

    int n    = blockIdx.x;
    int half = blockIdx.y;               // 0 or 1 -> channels [half*128, half*128+128)
    int warp = threadIdx.x >> 5;
    int lane = threadIdx.x & 31;

    const float* r = rois + n * 5;
    int   b  = (int)__ldg(r + 0);
    float sx = __ldg(r + 1) * 0.25f - 0.5f;
    float sy = __ldg(r + 2) * 0.25f - 0.5f;
    float ex = __ldg(r + 3) * 0.25f - 0.5f;
    float ey = __ldg(r + 4) * 0.25f - 0.5f;
    float bw = (ex - sx) / (float)OUTW;
    float bh = (ey - sy) / (float)OUTH;

    // base pointer for this block's channel chunk + lane's 4 channels
    const __half* fbase = g_feat16 + (size_t)b * (H_ * W_ * C_) + half * 128 + lane * 4;

    for (int bin = warp; bin < NBIN; bin += 8) {
        int ph = bin / OUTW;
        int pw = bin - ph * OUTW;

        float a0 = 0.0f, a1 = 0.0f, a2 = 0.0f, a3 = 0.0f;

        #pragma unroll
        for (int iy = 0; iy < 2; iy++) {
            float y = sy + ((float)ph + (0.25f + 0.5f * iy)) * bh;
            if (y > -1.0f && y < (float)H_) {
                float y0 = fmaxf(y, 0.0f);
                int ylo = (int)floorf(y0);
                int yhi;
                float ly;
                if (ylo >= H_ - 1) { ylo = H_ - 1; yhi = H_ - 1; ly = 0.0f; }
                else               { yhi = ylo + 1; ly = y0 - (float)ylo; }

                const __half* row0 = fbase + (size_t)ylo * (W_ * C_);
                const __half* row1 = fbase + (size_t)yhi * (W_ * C_);
                float wy1 = ly, wy0 = 1.0f - ly;

                #pragma unroll
                for (int ix = 0; ix < 2; ix++) {
                    float x = sx + ((float)pw + (0.25f + 0.5f * ix)) * bw;
                    if (x > -1.0f && x < (float)W_) {
                        float x0 = fmaxf(x, 0.0f);
                        int xlo = (int)floorf(x0);
                        int xhi;
                        float lx;
                        if (xlo >= W_ - 1) { xlo = W_ - 1; xhi = W_ - 1; lx = 0.0f; }
                        else               { xhi = xlo + 1; lx = x0 - (float)xlo; }

                        float wx1 = lx, wx0 = 1.0f - lx;
                        float w00 = wy0 * wx0, w01 = wy0 * wx1;
                        float w10 = wy1 * wx0, w11 = wy1 * wx1;

                        uint2 u00 = *(const uint2*)(row0 + (size_t)xlo * C_);
                        uint2 u01 = *(const uint2*)(row0 + (size_t)xhi * C_);
                        uint2 u10 = *(const uint2*)(row1 + (size_t)xlo * C_);
                        uint2 u11 = *(const uint2*)(row1 + (size_t)xhi * C_);

                        float2 f00a = __half22float2(*reinterpret_cast<__half2*>(&u00.x));
                        float2 f00b = __half22float2(*reinterpret_cast<__half2*>(&u00.y));
                        float2 f01a = __half22float2(*reinterpret_cast<__half2*>(&u01.x));
                        float2 f01b = __half22float2(*reinterpret_cast<__half2*>(&u01.y));
                        float2 f10a = __half22float2(*reinterpret_cast<__half2*>(&u10.x));
                        float2 f10b = __half22float2(*reinterpret_cast<__half2*>(&u10.y));
                        float2 f11a = __half22float2(*reinterpret_cast<__half2*>(&u11.x));
                        float2 f11b = __half22float2(*reinterpret_cast<__half2*>(&u11.y));

                        a0 += w00 * f00a.x + w01 * f01a.x + w10 * f10a.x + w11 * f11a.x;
                        a1 += w00 * f00a.y + w01 * f01a.y + w10 * f10a.y + w11 * f11a.y;
                        a2 += w00 * f00b.x + w01 * f01b.x + w10 * f10b.x + w11 * f11b.x;
                        a3 += w00 * f00b.y + w01 * f01b.y + w10 * f10b.y + w11 * f11b.y;
                    }
                }
            }
        }

        int cl = lane * 4;
        sout[(cl + 0) * NBIN + bin] = a0 * 0.25f;
        sout[(cl + 1) * NBIN + bin] = a1 * 0.25f;
        sout[(cl + 2) * NBIN + bin] = a2 * 0.25f;
        sout[(cl + 3) * NBIN + bin] = a3 * 0.25f;
    }
    __syncthreads();

    // coalesced store: this block owns out[n, half*128 : half*128+128, :, :]
    float* o = out + (size_t)n * (C_ * NBIN) + (size_t)half * 128 * NBIN;
    #pragma unroll
    for (int i = threadIdx.x; i < 128 * NBIN; i += 256)
        o[i] = sout[i];
}

extern "C" void kernel_launch(void* const* d_in, const int* in_sizes, int n_in,
                              void* d_out, int out_size)
{
    const float* feat = (const float*)d_in[0];
    const float* rois = (const float*)d_in[1];
    float* out = (float*)d_out;

    // Kernel 1: relayout NCHW fp32 -> NHWC fp16
    dim3 tgrid((W_ + 31) / 32, B_ * H_, C_ / 32);
    dim3 tblock(32, 8);
    transpose_kernel<<<tgrid, tblock>>>(feat);

    // Kernel 2: gather
    int n_rois = in_sizes[1] / 5;
    dim3 ggrid(n_rois, 2);
    roi_gather_kernel<<<ggrid, 256>>>(rois, out);
}

// round 3
// speedup vs baseline: 1.6774x; 1.0372x over previous
#include <cuda_runtime.h>
#include <cuda_fp16.h>

// RoIAlign via NHWC fp16 relayout + branch-free full-C gather.
// feat: (B=2, C=256, H=200, W=336) fp32 NCHW
// rois: (N=1000, 5) [bidx, x1, y1, x2, y2] fp32
// out:  (N, 256, 7, 7) fp32

#define B_    2
#define C_    256
#define H_    200
#define W_    336
#define OUTH  7
#define OUTW  7
#define NBIN  49
#define HWC   (H_ * W_ * C_)

// NHWC fp16 scratch: [B][H][W][C]
__device__ __half g_feat16[(size_t)B_ * HWC];

// ---------------------------------------------------------------------------
// Kernel 1: NCHW fp32 -> NHWC fp16. Block: 64 channels x 32 x-positions.
// Both gmem sides are 128B warp transactions.
// ---------------------------------------------------------------------------
__global__ __launch_bounds__(256) void transpose_kernel(const float* __restrict__ feat)
{
    __shared__ float tile[64][33];   // [c][x]

    int xt = blockIdx.x * 32;
    int by = blockIdx.y;             // b*H + y
    int b  = by / H_;
    int y  = by % H_;
    int c0 = blockIdx.z * 64;
    int tx = threadIdx.x;
    int ty = threadIdx.y;

    const float* src = feat + ((size_t)(b * C_ + c0) * H_ + y) * W_;
    int  xg  = xt + tx;
    bool xin = xg < W_;

    #pragma unroll
    for (int k = 0; k < 8; k++) {
        int c = ty + k * 8;
        tile[c][tx] = xin ? __ldg(src + (size_t)c * (H_ * W_) + xg) : 0.0f;
    }
    __syncthreads();

    __half* dst = g_feat16 + ((size_t)(b * H_ + y) * W_) * C_ + c0;
    #pragma unroll
    for (int k = 0; k < 4; k++) {
        int xl = ty + k * 8;
        int x  = xt + xl;
        if (x < W_) {
            __half2 v = __floats2half2_rn(tile[2 * tx][xl], tile[2 * tx + 1][xl]);
            *(__half2*)(dst + (size_t)x * C_ + 2 * tx) = v;
        }
    }
}

// ---------------------------------------------------------------------------
// Kernel 2: gather. One block per roi, 256 threads = 8 warps.
// Warp handles bins warp, warp+8, ...; lane covers 8 channels (uint4).
// Coordinates precomputed branch-free per block; validity folded into weights.
// ---------------------------------------------------------------------------
__global__ __launch_bounds__(256, 4) void roi_gather_kernel(
    const float* __restrict__ rois,
    float* __restrict__ out)
{
    extern __shared__ float smem[];
    float* sout  = smem;                       // 12576 floats (bank-skewed)
    int*   s_ylo = (int*)(smem + 12576);       // [14]
    int*   s_yhi = s_ylo + 14;                 // [14]
    int*   s_xlo = s_yhi + 14;                 // [14]
    int*   s_xhi = s_xlo + 14;                 // [14]
    float* s_wy0 = (float*)(s_xhi + 14);       // [14]
    float* s_wy1 = s_wy0 + 14;
    float* s_wx0 = s_wy1 + 14;
    float* s_wx1 = s_wx0 + 14;

    int n    = blockIdx.x;
    int tid  = threadIdx.x;
    int warp = tid >> 5;
    int lane = tid & 31;

    const float* r = rois + n * 5;
    int   b  = (int)__ldg(r + 0);
    float sx = __ldg(r + 1) * 0.25f - 0.5f;
    float sy = __ldg(r + 2) * 0.25f - 0.5f;
    float ex = __ldg(r + 3) * 0.25f - 0.5f;
    float ey = __ldg(r + 4) * 0.25f - 0.5f;
    float bw = (ex - sx) / (float)OUTW;
    float bh = (ey - sy) / (float)OUTH;

    // --- precompute y samples (threads 0..13) and x samples (threads 64..77) ---
    if (tid < 14) {
        int s  = tid;
        int ph = s >> 1, iy = s & 1;
        float y = sy + ((float)ph + (0.25f + 0.5f * iy)) * bh;
        bool valid = (y > -1.0f) && (y < (float)H_);
        float y0 = fmaxf(y, 0.0f);
        int ylo = (int)floorf(y0);
        int yhi; float ly;
        if (ylo >= H_ - 1) { ylo = H_ - 1; yhi = H_ - 1; ly = 0.0f; }
        else               { yhi = ylo + 1; ly = y0 - (float)ylo; }
        s_ylo[s] = ylo * (W_ * C_);
        s_yhi[s] = yhi * (W_ * C_);
        s_wy0[s] = valid ? (1.0f - ly) * 0.25f : 0.0f;
        s_wy1[s] = valid ? ly * 0.25f : 0.0f;
    } else if (tid >= 64 && tid < 78) {
        int s  = tid - 64;
        int pw = s >> 1, ix = s & 1;
        float x = sx + ((float)pw + (0.25f + 0.5f * ix)) * bw;
        bool valid = (x > -1.0f) && (x < (float)W_);
        float x0 = fmaxf(x, 0.0f);
        int xlo = (int)floorf(x0);
        int xhi; float lx;
        if (xlo >= W_ - 1) { xlo = W_ - 1; xhi = W_ - 1; lx = 0.0f; }
        else               { xhi = xlo + 1; lx = x0 - (float)xlo; }
        s_xlo[s] = xlo * C_;
        s_xhi[s] = xhi * C_;
        s_wx0[s] = valid ? (1.0f - lx) : 0.0f;
        s_wx1[s] = valid ? lx : 0.0f;
    }
    __syncthreads();

    const __half* fbase = g_feat16 + (size_t)b * HWC + lane * 8;

    for (int bin = warp; bin < NBIN; bin += 8) {
        int ph = bin / OUTW;
        int pw = bin - ph * OUTW;

        float a0 = 0.f, a1 = 0.f, a2 = 0.f, a3 = 0.f;
        float a4 = 0.f, a5 = 0.f, a6 = 0.f, a7 = 0.f;

        #pragma unroll
        for (int iy = 0; iy < 2; iy++) {
            int   syi = ph * 2 + iy;
            int   yo0 = s_ylo[syi], yo1 = s_yhi[syi];
            float wy0 = s_wy0[syi], wy1 = s_wy1[syi];

            #pragma unroll
            for (int ix = 0; ix < 2; ix++) {
                int   sxi = pw * 2 + ix;
                int   xo0 = s_xlo[sxi], xo1 = s_xhi[sxi];
                float wx0 = s_wx0[sxi], wx1 = s_wx1[sxi];

                uint4 u00 = *(const uint4*)(fbase + yo0 + xo0);
                uint4 u01 = *(const uint4*)(fbase + yo0 + xo1);
                uint4 u10 = *(const uint4*)(fbase + yo1 + xo0);
                uint4 u11 = *(const uint4*)(fbase + yo1 + xo1);

                float w00 = wy0 * wx0, w01 = wy0 * wx1;
                float w10 = wy1 * wx0, w11 = wy1 * wx1;

                float2 c00a = __half22float2(*reinterpret_cast<__half2*>(&u00.x));
                float2 c00b = __half22float2(*reinterpret_cast<__half2*>(&u00.y));
                float2 c00c = __half22float2(*reinterpret_cast<__half2*>(&u00.z));
                float2 c00d = __half22float2(*reinterpret_cast<__half2*>(&u00.w));
                a0 += w00 * c00a.x; a1 += w00 * c00a.y;
                a2 += w00 * c00b.x; a3 += w00 * c00b.y;
                a4 += w00 * c00c.x; a5 += w00 * c00c.y;
                a6 += w00 * c00d.x; a7 += w00 * c00d.y;

                float2 c01a = __half22float2(*reinterpret_cast<__half2*>(&u01.x));
                float2 c01b = __half22float2(*reinterpret_cast<__half2*>(&u01.y));
                float2 c01c = __half22float2(*reinterpret_cast<__half2*>(&u01.z));
                float2 c01d = __half22float2(*reinterpret_cast<__half2*>(&u01.w));
                a0 += w01 * c01a.x; a1 += w01 * c01a.y;
                a2 += w01 * c01b.x; a3 += w01 * c01b.y;
                a4 += w01 * c01c.x; a5 += w01 * c01c.y;
                a6 += w01 * c01d.x; a7 += w01 * c01d.y;

                float2 c10a = __half22float2(*reinterpret_cast<__half2*>(&u10.x));
                float2 c10b = __half22float2(*reinterpret_cast<__half2*>(&u10.y));
                float2 c10c = __half22float2(*reinterpret_cast<__half2*>(&u10.z));
                float2 c10d = __half22float2(*reinterpret_cast<__half2*>(&u10.w));
                a0 += w10 * c10a.x; a1 += w10 * c10a.y;
                a2 += w10 * c10b.x; a3 += w10 * c10b.y;
                a4 += w10 * c10c.x; a5 += w10 * c10c.y;
                a6 += w10 * c10d.x; a7 += w10 * c10d.y;

                float2 c11a = __half22float2(*reinterpret_cast<__half2*>(&u11.x));
                float2 c11b = __half22float2(*reinterpret_cast<__half2*>(&u11.y));
                float2 c11c = __half22float2(*reinterpret_cast<__half2*>(&u11.z));
                float2 c11d = __half22float2(*reinterpret_cast<__half2*>(&u11.w));
                a0 += w11 * c11a.x; a1 += w11 * c11a.y;
                a2 += w11 * c11b.x; a3 += w11 * c11b.y;
                a4 += w11 * c11c.x; a5 += w11 * c11c.y;
                a6 += w11 * c11d.x; a7 += w11 * c11d.y;
            }
        }

        // bank-skewed store: idx(c,bin) = c*49 + c/8 + bin  (lane stride 393 -> conflict-free)
        int c    = lane * 8;
        int base = c * NBIN + (c >> 3) + bin;
        sout[base]            = a0;
        sout[base + NBIN]     = a1;
        sout[base + 2 * NBIN] = a2;
        sout[base + 3 * NBIN] = a3;
        sout[base + 4 * NBIN] = a4;
        sout[base + 5 * NBIN] = a5;
        sout[base + 6 * NBIN] = a6;
        sout[base + 7 * NBIN] = a7;
    }
    __syncthreads();

    // coalesced writeout, undoing the skew
    float* o = out + (size_t)n * (C_ * NBIN);
    #pragma unroll 7
    for (int i = tid; i < C_ * NBIN; i += 256) {
        int c = i / NBIN;
        o[i] = sout[i + (c >> 3)];
    }
}

#define GATHER_SMEM (12576 * 4 + 14 * 8 * 4)

extern "C" void kernel_launch(void* const* d_in, const int* in_sizes, int n_in,
                              void* d_out, int out_size)
{
    const float* feat = (const float*)d_in[0];
    const float* rois = (const float*)d_in[1];
    float* out = (float*)d_out;

    cudaFuncSetAttribute(roi_gather_kernel,
                         cudaFuncAttributeMaxDynamicSharedMemorySize, GATHER_SMEM);

    dim3 tgrid((W_ + 31) / 32, B_ * H_, C_ / 64);
    dim3 tblock(32, 8);
    transpose_kernel<<<tgrid, tblock>>>(feat);

    int n_rois = in_sizes[1] / 5;
    roi_gather_kernel<<<n_rois, 256, GATHER_SMEM>>>(rois, out);
}